// round 2
// baseline (speedup 1.0000x reference)
#include <cuda_runtime.h>
#include <math.h>
#include <stdint.h>

#define BB 2
#define TT 2048
#define EE 1024
#define NHQ 16
#define NHKV 4
#define DD 64
#define GG 4

// Scratch (static __device__ per allocation rules): ~42MB total
__device__ float g_q[(size_t)BB*NHQ*TT*DD];   // (b, hq, t, d)
__device__ float g_k[(size_t)BB*NHKV*TT*DD];  // (b, hkv, t, d)
__device__ float g_v[(size_t)BB*NHKV*TT*DD];  // (b, hkv, t, d)
__device__ float g_y[(size_t)BB*TT*EE];       // (b, t, e) attention output pre-Wo

// ---------------------------------------------------------------------------
// Fused QKV GEMM: x(4096x1024) @ [Wq|Wk|Wv](1024x1536), epilogue writes
// head-major layouts into g_q/g_k/g_v with bias.
// Tile 128x128, BK=8, 256 threads, 8x8 per-thread micro-tile (split 4+4).
// ---------------------------------------------------------------------------
__global__ void __launch_bounds__(256) qkv_gemm_kernel(
    const float* __restrict__ x,
    const float* __restrict__ Wq, const float* __restrict__ bq,
    const float* __restrict__ Wk, const float* __restrict__ bk,
    const float* __restrict__ Wv, const float* __restrict__ bv)
{
    __shared__ float As[8][128];
    __shared__ float Bs[8][128];

    const int tid = threadIdx.x;
    const int m0 = blockIdx.x * 128;
    const int n0 = blockIdx.y * 128;   // global col in [0,1536)

    const float* Wmat; const float* bias; int ldw; int ncol0;
    if (n0 < 1024)      { Wmat = Wq; bias = bq; ldw = 1024; ncol0 = n0; }
    else if (n0 < 1280) { Wmat = Wk; bias = bk; ldw = 256;  ncol0 = n0 - 1024; }
    else                { Wmat = Wv; bias = bv; ldw = 256;  ncol0 = n0 - 1280; }

    const int arow = tid >> 1;          // 0..127
    const int acol = (tid & 1) * 4;     // 0 or 4
    const int brow = tid >> 5;          // 0..7
    const int bcol = (tid & 31) * 4;    // 0..124

    const float* Ag = x + (size_t)(m0 + arow) * 1024 + acol;
    const float* Bg = Wmat + (size_t)brow * ldw + ncol0 + bcol;

    const int ty4 = (tid >> 4) * 4;     // 0..60
    const int tx4 = (tid & 15) * 4;     // 0..60

    float acc[8][8];
#pragma unroll
    for (int i = 0; i < 8; i++)
#pragma unroll
        for (int j = 0; j < 8; j++) acc[i][j] = 0.f;

    for (int kt = 0; kt < 128; kt++) {
        float4 av  = *(const float4*)(Ag + kt * 8);
        float4 bv4 = *(const float4*)(Bg + (size_t)kt * 8 * ldw);
        __syncthreads();
        As[acol + 0][arow] = av.x;
        As[acol + 1][arow] = av.y;
        As[acol + 2][arow] = av.z;
        As[acol + 3][arow] = av.w;
        *(float4*)&Bs[brow][bcol] = bv4;
        __syncthreads();
#pragma unroll
        for (int kk = 0; kk < 8; kk++) {
            float4 a0 = *(float4*)&As[kk][ty4];
            float4 a1 = *(float4*)&As[kk][64 + ty4];
            float4 b0 = *(float4*)&Bs[kk][tx4];
            float4 b1 = *(float4*)&Bs[kk][64 + tx4];
            float ar[8] = {a0.x,a0.y,a0.z,a0.w,a1.x,a1.y,a1.z,a1.w};
            float br[8] = {b0.x,b0.y,b0.z,b0.w,b1.x,b1.y,b1.z,b1.w};
#pragma unroll
            for (int i = 0; i < 8; i++)
#pragma unroll
                for (int j = 0; j < 8; j++)
                    acc[i][j] = fmaf(ar[i], br[j], acc[i][j]);
        }
    }

#pragma unroll
    for (int i = 0; i < 8; i++) {
        const int m = m0 + ((i < 4) ? (ty4 + i) : (64 + ty4 + i - 4));
        const int b = m >> 11;
        const int t = m & 2047;
#pragma unroll
        for (int j = 0; j < 8; j++) {
            const int nloc = ((j < 4) ? (tx4 + j) : (64 + tx4 + j - 4));
            const int n = n0 + nloc;           // global col 0..1535
            const int ncl = ncol0 + nloc;      // col within its matrix
            const float val = acc[i][j] + bias[ncl];
            if (n < 1024) {
                const int head = n >> 6, d = n & 63;
                g_q[(((size_t)b * NHQ + head) * TT + t) * DD + d] = val;
            } else if (n < 1280) {
                const int c = n - 1024;
                g_k[(((size_t)b * NHKV + (c >> 6)) * TT + t) * DD + (c & 63)] = val;
            } else {
                const int c = n - 1280;
                g_v[(((size_t)b * NHKV + (c >> 6)) * TT + t) * DD + (c & 63)] = val;
            }
        }
    }
}

// ---------------------------------------------------------------------------
// Out projection: g_y(4096x1024) @ Wo(1024x1024) + bo -> out (row-major)
// ---------------------------------------------------------------------------
__global__ void __launch_bounds__(256) out_gemm_kernel(
    const float* __restrict__ Wo, const float* __restrict__ bo,
    float* __restrict__ out)
{
    __shared__ float As[8][128];
    __shared__ float Bs[8][128];

    const int tid = threadIdx.x;
    const int m0 = blockIdx.x * 128;
    const int n0 = blockIdx.y * 128;

    const int arow = tid >> 1;
    const int acol = (tid & 1) * 4;
    const int brow = tid >> 5;
    const int bcol = (tid & 31) * 4;

    const float* Ag = g_y + (size_t)(m0 + arow) * 1024 + acol;
    const float* Bg = Wo + (size_t)brow * 1024 + n0 + bcol;

    const int ty4 = (tid >> 4) * 4;
    const int tx4 = (tid & 15) * 4;

    float acc[8][8];
#pragma unroll
    for (int i = 0; i < 8; i++)
#pragma unroll
        for (int j = 0; j < 8; j++) acc[i][j] = 0.f;

    for (int kt = 0; kt < 128; kt++) {
        float4 av  = *(const float4*)(Ag + kt * 8);
        float4 bv4 = *(const float4*)(Bg + (size_t)kt * 8 * 1024);
        __syncthreads();
        As[acol + 0][arow] = av.x;
        As[acol + 1][arow] = av.y;
        As[acol + 2][arow] = av.z;
        As[acol + 3][arow] = av.w;
        *(float4*)&Bs[brow][bcol] = bv4;
        __syncthreads();
#pragma unroll
        for (int kk = 0; kk < 8; kk++) {
            float4 a0 = *(float4*)&As[kk][ty4];
            float4 a1 = *(float4*)&As[kk][64 + ty4];
            float4 b0 = *(float4*)&Bs[kk][tx4];
            float4 b1 = *(float4*)&Bs[kk][64 + tx4];
            float ar[8] = {a0.x,a0.y,a0.z,a0.w,a1.x,a1.y,a1.z,a1.w};
            float br[8] = {b0.x,b0.y,b0.z,b0.w,b1.x,b1.y,b1.z,b1.w};
#pragma unroll
            for (int i = 0; i < 8; i++)
#pragma unroll
                for (int j = 0; j < 8; j++)
                    acc[i][j] = fmaf(ar[i], br[j], acc[i][j]);
        }
    }

#pragma unroll
    for (int i = 0; i < 8; i++) {
        const int m = m0 + ((i < 4) ? (ty4 + i) : (64 + ty4 + i - 4));
#pragma unroll
        for (int j = 0; j < 8; j++) {
            const int n = n0 + ((j < 4) ? (tx4 + j) : (64 + tx4 + j - 4));
            out[(size_t)m * 1024 + n] = acc[i][j] + bo[n];
        }
    }
}

// ---------------------------------------------------------------------------
// RoPE, in place on g_q (isq=1) or g_k (isq=0). One thread per (bh, t, p<32).
// Matches reference: fp32 theta, fp32 angle=(t+1)*theta, accurate sin/cos of
// that exact fp32 angle via double range reduction.
// ---------------------------------------------------------------------------
__global__ void rope_kernel(int isq, int total)
{
    const int idx = blockIdx.x * 256 + threadIdx.x;
    if (idx >= total) return;
    float* buf = isq ? g_q : g_k;
    const int p  = idx & 31;
    const int t  = (idx >> 5) & 2047;
    const int bh = idx >> 16;
    float* row = buf + ((size_t)bh * TT + t) * DD;

    const double theta_d = pow(10000.0, -(double)p * (1.0 / 32.0));
    const float  theta_f = (float)theta_d;
    const float  ang     = (float)(t + 1) * theta_f;
    const double r       = fmod((double)ang, 6.283185307179586476925287);
    const float  rf      = (float)r;
    const float  s = sinf(rf);
    const float  c = cosf(rf);

    const float x1 = row[p];
    const float x2 = row[p + 32];
    row[p]      = x1 * c - x2 * s;
    row[p + 32] = x2 * c + x1 * s;
}

// ---------------------------------------------------------------------------
// Attention: one CTA per (b, hq, 16-query tile). Scores (16x2048) live in
// SMEM; K/V tiles staged as padded float4 (conflict-free LDS.128).
// Writes normalized att_weights to d_out and PV result into g_y.
// ---------------------------------------------------------------------------
__global__ void __launch_bounds__(256) attn_kernel(float* __restrict__ att_out,
                                                   int write_att)
{
    extern __shared__ float sm[];
    float*  S      = sm;                          // [16][2048]
    float4* kv4    = (float4*)(sm + 16 * 2048);   // [64][17] padded
    float4* q4t    = kv4 + 64 * 17;               // [16][17] padded
    float*  rowinv = (float*)(q4t + 16 * 17);     // [16]

    const int qtile = blockIdx.x;                 // 0..127
    const int bh    = blockIdx.y;                 // 0..31
    const int b  = bh >> 4, hq = bh & 15;
    const int h  = hq >> 2, g  = hq & 3;
    const int tid  = threadIdx.x;
    const int warp = tid >> 5, lane = tid & 31;

    const float* qbase = g_q + (((size_t)(b * NHQ + hq)) * TT + qtile * 16) * DD;
    const float* kbase = g_k + ((size_t)(b * NHKV + h)) * TT * DD;
    const float* vbase = g_v + ((size_t)(b * NHKV + h)) * TT * DD;

    // load q tile (scaled by 1/sqrt(D))
    {
        const int r = tid >> 4, c = tid & 15;
        float4 qv = *(const float4*)(qbase + r * 64 + c * 4);
        qv.x *= 0.125f; qv.y *= 0.125f; qv.z *= 0.125f; qv.w *= 0.125f;
        q4t[r * 17 + c] = qv;
    }

    const int tq_hi  = qtile * 16 + 15;
    const int ntiles = tq_hi / 64 + 1;
    const int Jlim   = ntiles * 64;

    // ---- QK^T: warp handles 2 query rows; lane handles keys (lane, lane+32)
    const int q0 = warp * 2, q1 = q0 + 1;
    for (int kt = 0; kt < ntiles; kt++) {
        const int j0 = kt * 64;
        __syncthreads();
#pragma unroll
        for (int i = 0; i < 4; i++) {
            const int idx = tid + i * 256;
            kv4[(idx >> 4) * 17 + (idx & 15)] =
                *(const float4*)(kbase + (size_t)(j0 + (idx >> 4)) * 64 + (idx & 15) * 4);
        }
        __syncthreads();
        float s00 = 0.f, s01 = 0.f, s10 = 0.f, s11 = 0.f;
#pragma unroll
        for (int c = 0; c < 16; c++) {
            const float4 kA = kv4[lane * 17 + c];
            const float4 kB = kv4[(lane + 32) * 17 + c];
            const float4 qa = q4t[q0 * 17 + c];
            const float4 qb = q4t[q1 * 17 + c];
            s00 = fmaf(qa.x,kA.x,s00); s00 = fmaf(qa.y,kA.y,s00); s00 = fmaf(qa.z,kA.z,s00); s00 = fmaf(qa.w,kA.w,s00);
            s01 = fmaf(qa.x,kB.x,s01); s01 = fmaf(qa.y,kB.y,s01); s01 = fmaf(qa.z,kB.z,s01); s01 = fmaf(qa.w,kB.w,s01);
            s10 = fmaf(qb.x,kA.x,s10); s10 = fmaf(qb.y,kA.y,s10); s10 = fmaf(qb.z,kA.z,s10); s10 = fmaf(qb.w,kA.w,s10);
            s11 = fmaf(qb.x,kB.x,s11); s11 = fmaf(qb.y,kB.y,s11); s11 = fmaf(qb.z,kB.z,s11); s11 = fmaf(qb.w,kB.w,s11);
        }
        S[q0 * 2048 + j0 + lane]      = s00;
        S[q0 * 2048 + j0 + 32 + lane] = s01;
        S[q1 * 2048 + j0 + lane]      = s10;
        S[q1 * 2048 + j0 + 32 + lane] = s11;
    }
    __syncthreads();

    // ---- softmax per row (causal): warp handles rows 2w, 2w+1
#pragma unroll
    for (int rr = 0; rr < 2; rr++) {
        const int r  = warp * 2 + rr;
        const int tq = qtile * 16 + r;
        const int L  = tq + 1;
        float m = -3.4e38f;
        for (int j = lane; j < L; j += 32) m = fmaxf(m, S[r * 2048 + j]);
#pragma unroll
        for (int o = 16; o; o >>= 1) m = fmaxf(m, __shfl_xor_sync(0xffffffffu, m, o));
        float sum = 0.f;
        for (int j = lane; j < Jlim; j += 32) {
            const float sv = S[r * 2048 + j];
            const float e  = (j < L) ? __expf(sv - m) : 0.f;
            S[r * 2048 + j] = e;
            sum += e;
        }
#pragma unroll
        for (int o = 16; o; o >>= 1) sum += __shfl_xor_sync(0xffffffffu, sum, o);
        const float inv = 1.f / sum;
        if (lane == 0) rowinv[r] = inv;
        if (write_att) {
            float* orow = att_out + ((((size_t)b * GG + g) * NHKV + h) * TT + tq) * TT;
            for (int j4 = lane * 4; j4 < Jlim; j4 += 128) {
                float4 e4 = *(float4*)&S[r * 2048 + j4];
                e4.x *= inv; e4.y *= inv; e4.z *= inv; e4.w *= inv;
                *(float4*)&orow[j4] = e4;
            }
            const float4 z4 = make_float4(0.f, 0.f, 0.f, 0.f);
            for (int j4 = Jlim + lane * 4; j4 < TT; j4 += 128)
                *(float4*)&orow[j4] = z4;
        }
    }

    // ---- PV: thread = (dim chunk dc, j segment js); 16 query accumulators
    const int dc = tid & 15;
    const int js = tid >> 4;
    float4 acc[16];
#pragma unroll
    for (int q = 0; q < 16; q++) acc[q] = make_float4(0.f, 0.f, 0.f, 0.f);

    for (int kt = 0; kt < ntiles; kt++) {
        const int j0 = kt * 64;
        __syncthreads();
#pragma unroll
        for (int i = 0; i < 4; i++) {
            const int idx = tid + i * 256;
            kv4[(idx >> 4) * 17 + (idx & 15)] =
                *(const float4*)(vbase + (size_t)(j0 + (idx >> 4)) * 64 + (idx & 15) * 4);
        }
        __syncthreads();
#pragma unroll
        for (int u = 0; u < 4; u++) {
            const int jj = js + u * 16;
            const float4 vv = kv4[jj * 17 + dc];
#pragma unroll
            for (int q = 0; q < 16; q++) {
                const float e = S[q * 2048 + j0 + jj];
                acc[q].x = fmaf(e, vv.x, acc[q].x);
                acc[q].y = fmaf(e, vv.y, acc[q].y);
                acc[q].z = fmaf(e, vv.z, acc[q].z);
                acc[q].w = fmaf(e, vv.w, acc[q].w);
            }
        }
    }

    // reduce over js (16 partials per (q,dc)); reuse S as scratch
    __syncthreads();
    float4* P = (float4*)S;   // [js][q*16+dc] : 16*256 float4 = 64KB <= 128KB
#pragma unroll
    for (int q = 0; q < 16; q++) P[js * 256 + q * 16 + dc] = acc[q];
    __syncthreads();
    {
        const int q2 = tid >> 4, dc2 = tid & 15;
        float4 r4 = make_float4(0.f, 0.f, 0.f, 0.f);
#pragma unroll
        for (int js2 = 0; js2 < 16; js2++) {
            const float4 pv = P[js2 * 256 + q2 * 16 + dc2];
            r4.x += pv.x; r4.y += pv.y; r4.z += pv.z; r4.w += pv.w;
        }
        const float inv = rowinv[q2];
        r4.x *= inv; r4.y *= inv; r4.z *= inv; r4.w *= inv;
        const int tq = qtile * 16 + q2;
        float* ydst = g_y + ((size_t)b * TT + tq) * EE + hq * 64 + dc2 * 4;
        *(float4*)ydst = r4;
    }
}

// ---------------------------------------------------------------------------
extern "C" void kernel_launch(void* const* d_in, const int* in_sizes, int n_in,
                              void* d_out, int out_size)
{
    const float* x  = (const float*)d_in[0];
    // d_in[1] = mask (int32, triu(...,1)) -> causal, handled analytically
    const float* Wq = (const float*)d_in[2];
    const float* bq = (const float*)d_in[3];
    const float* Wk = (const float*)d_in[4];
    const float* bk = (const float*)d_in[5];
    const float* Wv = (const float*)d_in[6];
    const float* bv = (const float*)d_in[7];
    const float* Wo = (const float*)d_in[8];
    const float* bo = (const float*)d_in[9];

    float* out = (float*)d_out;
    const size_t y_elems   = (size_t)BB * TT * EE;                 // 4,194,304
    const size_t att_elems = (size_t)BB * NHQ * TT * TT;           // 134,217,728
    float* attOut = out + y_elems;
    const int write_att = ((size_t)out_size >= y_elems + att_elems) ? 1 : 0;

    const size_t ATTN_SMEM = (size_t)(16 * 2048 + 64 * 17 * 4 + 16 * 17 * 4 + 16) * sizeof(float);
    cudaFuncSetAttribute(attn_kernel, cudaFuncAttributeMaxDynamicSharedMemorySize,
                         (int)ATTN_SMEM);

    qkv_gemm_kernel<<<dim3(32, 12), 256>>>(x, Wq, bq, Wk, bk, Wv, bv);

    const int qpairs = BB * NHQ * TT * 32;   // 2,097,152
    const int kpairs = BB * NHKV * TT * 32;  //   524,288
    rope_kernel<<<(qpairs + 255) / 256, 256>>>(1, qpairs);
    rope_kernel<<<(kpairs + 255) / 256, 256>>>(0, kpairs);

    attn_kernel<<<dim3(128, 32), 256, ATTN_SMEM>>>(attOut, write_att);

    out_gemm_kernel<<<dim3(32, 8), 256>>>(Wo, bo, out);
}

// round 3
// speedup vs baseline: 1.0615x; 1.0615x over previous
#include <cuda_runtime.h>
#include <math.h>
#include <stdint.h>

#define BB 2
#define TT 2048
#define EE 1024
#define NHQ 16
#define NHKV 4
#define DD 64
#define GG 4

typedef unsigned long long u64;

// ---- packed f32x2 helpers (sm_100+) --------------------------------------
__device__ __forceinline__ u64 pk2(float lo, float hi) {
    u64 r; asm("mov.b64 %0,{%1,%2};" : "=l"(r) : "f"(lo), "f"(hi)); return r;
}
__device__ __forceinline__ float2 upk2(u64 v) {
    float2 f; asm("mov.b64 {%0,%1},%2;" : "=f"(f.x), "=f"(f.y) : "l"(v)); return f;
}
__device__ __forceinline__ void fma2(u64& d, u64 a, u64 b) {
    asm("fma.rn.f32x2 %0,%1,%2,%0;" : "+l"(d) : "l"(a), "l"(b));
}

// Scratch (static __device__ per allocation rules)
__device__ float g_q[(size_t)BB*NHQ*TT*DD];   // (b, hq, t, d)
__device__ float g_k[(size_t)BB*NHKV*TT*DD];  // (b, hkv, t, d)
__device__ float g_v[(size_t)BB*NHKV*TT*DD];  // (b, hkv, t, d)
__device__ float g_y[(size_t)BB*TT*EE];       // (b, t, e) attention output pre-Wo

// ---------------------------------------------------------------------------
// Fused QKV GEMM: x(4096x1024) @ [Wq|Wk|Wv](1024x1536), FFMA2 micro-kernel.
// ---------------------------------------------------------------------------
__global__ void __launch_bounds__(256) qkv_gemm_kernel(
    const float* __restrict__ x,
    const float* __restrict__ Wq, const float* __restrict__ bq,
    const float* __restrict__ Wk, const float* __restrict__ bk,
    const float* __restrict__ Wv, const float* __restrict__ bv)
{
    __shared__ float As[8][128];
    __shared__ float Bs[8][128];

    const int tid = threadIdx.x;
    const int m0 = blockIdx.x * 128;
    const int n0 = blockIdx.y * 128;   // global col in [0,1536)

    const float* Wmat; const float* bias; int ldw; int ncol0;
    if (n0 < 1024)      { Wmat = Wq; bias = bq; ldw = 1024; ncol0 = n0; }
    else if (n0 < 1280) { Wmat = Wk; bias = bk; ldw = 256;  ncol0 = n0 - 1024; }
    else                { Wmat = Wv; bias = bv; ldw = 256;  ncol0 = n0 - 1280; }

    const int arow = tid >> 1;          // 0..127
    const int acol = (tid & 1) * 4;     // 0 or 4
    const int brow = tid >> 5;          // 0..7
    const int bcol = (tid & 31) * 4;    // 0..124

    const float* Ag = x + (size_t)(m0 + arow) * 1024 + acol;
    const float* Bg = Wmat + (size_t)brow * ldw + ncol0 + bcol;

    const int ty4 = (tid >> 4) * 4;     // 0..60
    const int tx4 = (tid & 15) * 4;     // 0..60

    u64 acc2[8][4];
#pragma unroll
    for (int i = 0; i < 8; i++)
#pragma unroll
        for (int j = 0; j < 4; j++) acc2[i][j] = 0ull;

    for (int kt = 0; kt < 128; kt++) {
        float4 av  = *(const float4*)(Ag + kt * 8);
        float4 bv4 = *(const float4*)(Bg + (size_t)kt * 8 * ldw);
        __syncthreads();
        As[acol + 0][arow] = av.x;
        As[acol + 1][arow] = av.y;
        As[acol + 2][arow] = av.z;
        As[acol + 3][arow] = av.w;
        *(float4*)&Bs[brow][bcol] = bv4;
        __syncthreads();
#pragma unroll
        for (int kk = 0; kk < 8; kk++) {
            float4 a0 = *(float4*)&As[kk][ty4];
            float4 a1 = *(float4*)&As[kk][64 + ty4];
            float4 b0 = *(float4*)&Bs[kk][tx4];
            float4 b1 = *(float4*)&Bs[kk][64 + tx4];
            float ar[8] = {a0.x,a0.y,a0.z,a0.w,a1.x,a1.y,a1.z,a1.w};
            u64 brp[4] = {pk2(b0.x,b0.y), pk2(b0.z,b0.w),
                          pk2(b1.x,b1.y), pk2(b1.z,b1.w)};
#pragma unroll
            for (int i = 0; i < 8; i++) {
                const u64 arp = pk2(ar[i], ar[i]);
#pragma unroll
                for (int j = 0; j < 4; j++)
                    fma2(acc2[i][j], arp, brp[j]);
            }
        }
    }

#pragma unroll
    for (int i = 0; i < 8; i++) {
        const int m = m0 + ((i < 4) ? (ty4 + i) : (64 + ty4 + i - 4));
        const int b = m >> 11;
        const int t = m & 2047;
#pragma unroll
        for (int j4 = 0; j4 < 4; j4++) {
            const float2 v2 = upk2(acc2[i][j4]);
            const int nbase = (j4 < 2) ? (tx4 + 2*j4) : (64 + tx4 + 2*(j4-2));
#pragma unroll
            for (int s = 0; s < 2; s++) {
                const int nloc = nbase + s;
                const int n = n0 + nloc;
                const int ncl = ncol0 + nloc;
                const float val = ((s == 0) ? v2.x : v2.y) + bias[ncl];
                if (n < 1024) {
                    const int head = n >> 6, d = n & 63;
                    g_q[(((size_t)b * NHQ + head) * TT + t) * DD + d] = val;
                } else if (n < 1280) {
                    const int c = n - 1024;
                    g_k[(((size_t)b * NHKV + (c >> 6)) * TT + t) * DD + (c & 63)] = val;
                } else {
                    const int c = n - 1280;
                    g_v[(((size_t)b * NHKV + (c >> 6)) * TT + t) * DD + (c & 63)] = val;
                }
            }
        }
    }
}

// ---------------------------------------------------------------------------
// Out projection: g_y(4096x1024) @ Wo(1024x1024) + bo -> out, FFMA2.
// ---------------------------------------------------------------------------
__global__ void __launch_bounds__(256) out_gemm_kernel(
    const float* __restrict__ Wo, const float* __restrict__ bo,
    float* __restrict__ out)
{
    __shared__ float As[8][128];
    __shared__ float Bs[8][128];

    const int tid = threadIdx.x;
    const int m0 = blockIdx.x * 128;
    const int n0 = blockIdx.y * 128;

    const int arow = tid >> 1;
    const int acol = (tid & 1) * 4;
    const int brow = tid >> 5;
    const int bcol = (tid & 31) * 4;

    const float* Ag = g_y + (size_t)(m0 + arow) * 1024 + acol;
    const float* Bg = Wo + (size_t)brow * 1024 + n0 + bcol;

    const int ty4 = (tid >> 4) * 4;
    const int tx4 = (tid & 15) * 4;

    u64 acc2[8][4];
#pragma unroll
    for (int i = 0; i < 8; i++)
#pragma unroll
        for (int j = 0; j < 4; j++) acc2[i][j] = 0ull;

    for (int kt = 0; kt < 128; kt++) {
        float4 av  = *(const float4*)(Ag + kt * 8);
        float4 bv4 = *(const float4*)(Bg + (size_t)kt * 8 * 1024);
        __syncthreads();
        As[acol + 0][arow] = av.x;
        As[acol + 1][arow] = av.y;
        As[acol + 2][arow] = av.z;
        As[acol + 3][arow] = av.w;
        *(float4*)&Bs[brow][bcol] = bv4;
        __syncthreads();
#pragma unroll
        for (int kk = 0; kk < 8; kk++) {
            float4 a0 = *(float4*)&As[kk][ty4];
            float4 a1 = *(float4*)&As[kk][64 + ty4];
            float4 b0 = *(float4*)&Bs[kk][tx4];
            float4 b1 = *(float4*)&Bs[kk][64 + tx4];
            float ar[8] = {a0.x,a0.y,a0.z,a0.w,a1.x,a1.y,a1.z,a1.w};
            u64 brp[4] = {pk2(b0.x,b0.y), pk2(b0.z,b0.w),
                          pk2(b1.x,b1.y), pk2(b1.z,b1.w)};
#pragma unroll
            for (int i = 0; i < 8; i++) {
                const u64 arp = pk2(ar[i], ar[i]);
#pragma unroll
                for (int j = 0; j < 4; j++)
                    fma2(acc2[i][j], arp, brp[j]);
            }
        }
    }

#pragma unroll
    for (int i = 0; i < 8; i++) {
        const int m = m0 + ((i < 4) ? (ty4 + i) : (64 + ty4 + i - 4));
#pragma unroll
        for (int j4 = 0; j4 < 4; j4++) {
            const float2 v2 = upk2(acc2[i][j4]);
            const int nbase = (j4 < 2) ? (tx4 + 2*j4) : (64 + tx4 + 2*(j4-2));
            const int n = n0 + nbase;
            out[(size_t)m * 1024 + n]     = v2.x + bo[n];
            out[(size_t)m * 1024 + n + 1] = v2.y + bo[n + 1];
        }
    }
}

// ---------------------------------------------------------------------------
// RoPE, in place on g_q (isq=1) or g_k (isq=0).
// ---------------------------------------------------------------------------
__global__ void rope_kernel(int isq, int total)
{
    const int idx = blockIdx.x * 256 + threadIdx.x;
    if (idx >= total) return;
    float* buf = isq ? g_q : g_k;
    const int p  = idx & 31;
    const int t  = (idx >> 5) & 2047;
    const int bh = idx >> 16;
    float* row = buf + ((size_t)bh * TT + t) * DD;

    const double theta_d = pow(10000.0, -(double)p * (1.0 / 32.0));
    const float  theta_f = (float)theta_d;
    const float  ang     = (float)(t + 1) * theta_f;
    const double r       = fmod((double)ang, 6.283185307179586476925287);
    const float  rf      = (float)r;
    const float  s = sinf(rf);
    const float  c = cosf(rf);

    const float x1 = row[p];
    const float x2 = row[p + 32];
    row[p]      = x1 * c - x2 * s;
    row[p + 32] = x2 * c + x1 * s;
}

// ---------------------------------------------------------------------------
// Attention: one CTA per (b, hq, 16-query tile). Scores (16x2048) in SMEM.
// QK: 128-wide K tiles, per-warp 2 rows x 4 keys/lane, FFMA2 (3B/FMA).
// PV: FFMA2 accumulation. K/V staged as padded float4 (conflict-free).
// ---------------------------------------------------------------------------
__global__ void __launch_bounds__(256) attn_kernel(float* __restrict__ att_out,
                                                   int write_att)
{
    extern __shared__ float sm[];
    float*  S      = sm;                          // [16][2048]
    float4* kv4    = (float4*)(sm + 16 * 2048);   // [128][17] padded
    float4* q4t    = kv4 + 128 * 17;              // [16][17] padded
    float*  rowinv = (float*)(q4t + 16 * 17);     // [16]

    const int qtile = blockIdx.x;                 // 0..127
    const int bh    = blockIdx.y;                 // 0..31
    const int b  = bh >> 4, hq = bh & 15;
    const int h  = hq >> 2, g  = hq & 3;
    const int tid  = threadIdx.x;
    const int warp = tid >> 5, lane = tid & 31;

    const float* qbase = g_q + (((size_t)(b * NHQ + hq)) * TT + qtile * 16) * DD;
    const float* kbase = g_k + ((size_t)(b * NHKV + h)) * TT * DD;
    const float* vbase = g_v + ((size_t)(b * NHKV + h)) * TT * DD;

    // load q tile (scaled by 1/sqrt(D))
    {
        const int r = tid >> 4, c = tid & 15;
        float4 qv = *(const float4*)(qbase + r * 64 + c * 4);
        qv.x *= 0.125f; qv.y *= 0.125f; qv.z *= 0.125f; qv.w *= 0.125f;
        q4t[r * 17 + c] = qv;
    }

    const int tq_hi  = qtile * 16 + 15;
    const int ntiles = tq_hi / 128 + 1;           // 128-wide tiles
    const int Jlim   = ntiles * 128;

    const u64* qu  = (const u64*)q4t;
    const u64* kvu = (const u64*)kv4;

    // ---- QK^T: warp handles 2 query rows; lane handles 4 keys (+0,32,64,96)
    const int q0 = warp * 2, q1 = q0 + 1;
    for (int kt = 0; kt < ntiles; kt++) {
        const int j0 = kt * 128;
        __syncthreads();
#pragma unroll
        for (int i = 0; i < 8; i++) {
            const int idx = tid + i * 256;
            kv4[(idx >> 4) * 17 + (idx & 15)] =
                *(const float4*)(kbase + (size_t)(j0 + (idx >> 4)) * 64 + (idx & 15) * 4);
        }
        __syncthreads();
        u64 acc[2][4];
#pragma unroll
        for (int r = 0; r < 2; r++)
#pragma unroll
            for (int kk = 0; kk < 4; kk++) acc[r][kk] = 0ull;
#pragma unroll
        for (int c = 0; c < 16; c++) {
            const u64 qa0 = qu[(q0 * 17 + c) * 2];
            const u64 qa1 = qu[(q0 * 17 + c) * 2 + 1];
            const u64 qb0 = qu[(q1 * 17 + c) * 2];
            const u64 qb1 = qu[(q1 * 17 + c) * 2 + 1];
#pragma unroll
            for (int kk = 0; kk < 4; kk++) {
                const int kr = lane + 32 * kk;
                const u64 k0 = kvu[(kr * 17 + c) * 2];
                const u64 k1 = kvu[(kr * 17 + c) * 2 + 1];
                fma2(acc[0][kk], qa0, k0); fma2(acc[0][kk], qa1, k1);
                fma2(acc[1][kk], qb0, k0); fma2(acc[1][kk], qb1, k1);
            }
        }
#pragma unroll
        for (int kk = 0; kk < 4; kk++) {
            const float2 a = upk2(acc[0][kk]);
            const float2 c2 = upk2(acc[1][kk]);
            S[q0 * 2048 + j0 + lane + 32 * kk] = a.x + a.y;
            S[q1 * 2048 + j0 + lane + 32 * kk] = c2.x + c2.y;
        }
    }
    __syncthreads();

    // ---- softmax per row (causal): warp handles rows 2w, 2w+1
#pragma unroll
    for (int rr = 0; rr < 2; rr++) {
        const int r  = warp * 2 + rr;
        const int tq = qtile * 16 + r;
        const int L  = tq + 1;
        float m = -3.4e38f;
        for (int j = lane; j < L; j += 32) m = fmaxf(m, S[r * 2048 + j]);
#pragma unroll
        for (int o = 16; o; o >>= 1) m = fmaxf(m, __shfl_xor_sync(0xffffffffu, m, o));
        float sum = 0.f;
        for (int j = lane; j < Jlim; j += 32) {
            const float sv = S[r * 2048 + j];
            const float e  = (j < L) ? __expf(sv - m) : 0.f;
            S[r * 2048 + j] = e;
            sum += e;
        }
#pragma unroll
        for (int o = 16; o; o >>= 1) sum += __shfl_xor_sync(0xffffffffu, sum, o);
        const float inv = 1.f / sum;
        if (lane == 0) rowinv[r] = inv;
        if (write_att) {
            float* orow = att_out + ((((size_t)b * GG + g) * NHKV + h) * TT + tq) * TT;
            for (int j4 = lane * 4; j4 < Jlim; j4 += 128) {
                float4 e4 = *(float4*)&S[r * 2048 + j4];
                e4.x *= inv; e4.y *= inv; e4.z *= inv; e4.w *= inv;
                *(float4*)&orow[j4] = e4;
            }
            const float4 z4 = make_float4(0.f, 0.f, 0.f, 0.f);
            for (int j4 = Jlim + lane * 4; j4 < TT; j4 += 128)
                *(float4*)&orow[j4] = z4;
        }
    }

    // ---- PV: thread = (dim chunk dc, j segment js); 16 query accumulators
    const int dc = tid & 15;
    const int js = tid >> 4;
    u64 accP[16][2];
#pragma unroll
    for (int q = 0; q < 16; q++) { accP[q][0] = 0ull; accP[q][1] = 0ull; }

    for (int kt = 0; kt < ntiles; kt++) {
        const int j0 = kt * 128;
        __syncthreads();
#pragma unroll
        for (int i = 0; i < 8; i++) {
            const int idx = tid + i * 256;
            kv4[(idx >> 4) * 17 + (idx & 15)] =
                *(const float4*)(vbase + (size_t)(j0 + (idx >> 4)) * 64 + (idx & 15) * 4);
        }
        __syncthreads();
#pragma unroll
        for (int u = 0; u < 8; u++) {
            const int jj = js + u * 16;
            const u64 v0 = kvu[(jj * 17 + dc) * 2];
            const u64 v1 = kvu[(jj * 17 + dc) * 2 + 1];
#pragma unroll
            for (int q = 0; q < 16; q++) {
                const float e = S[q * 2048 + j0 + jj];
                const u64 ep = pk2(e, e);
                fma2(accP[q][0], ep, v0);
                fma2(accP[q][1], ep, v1);
            }
        }
    }

    // reduce over js (16 partials per (q,dc)); reuse S as scratch
    __syncthreads();
    float4* P = (float4*)S;   // [js][q*16+dc] : 16*256 float4 = 64KB
#pragma unroll
    for (int q = 0; q < 16; q++) {
        const float2 xy = upk2(accP[q][0]);
        const float2 zw = upk2(accP[q][1]);
        P[js * 256 + q * 16 + dc] = make_float4(xy.x, xy.y, zw.x, zw.y);
    }
    __syncthreads();
    {
        const int q2 = tid >> 4, dc2 = tid & 15;
        float4 r4 = make_float4(0.f, 0.f, 0.f, 0.f);
#pragma unroll
        for (int js2 = 0; js2 < 16; js2++) {
            const float4 pv = P[js2 * 256 + q2 * 16 + dc2];
            r4.x += pv.x; r4.y += pv.y; r4.z += pv.z; r4.w += pv.w;
        }
        const float inv = rowinv[q2];
        r4.x *= inv; r4.y *= inv; r4.z *= inv; r4.w *= inv;
        const int tq = qtile * 16 + q2;
        float* ydst = g_y + ((size_t)b * TT + tq) * EE + hq * 64 + dc2 * 4;
        *(float4*)ydst = r4;
    }
}

// ---------------------------------------------------------------------------
extern "C" void kernel_launch(void* const* d_in, const int* in_sizes, int n_in,
                              void* d_out, int out_size)
{
    const float* x  = (const float*)d_in[0];
    // d_in[1] = mask (int32, triu(...,1)) -> causal, handled analytically
    const float* Wq = (const float*)d_in[2];
    const float* bq = (const float*)d_in[3];
    const float* Wk = (const float*)d_in[4];
    const float* bk = (const float*)d_in[5];
    const float* Wv = (const float*)d_in[6];
    const float* bv = (const float*)d_in[7];
    const float* Wo = (const float*)d_in[8];
    const float* bo = (const float*)d_in[9];

    float* out = (float*)d_out;
    const size_t y_elems   = (size_t)BB * TT * EE;                 // 4,194,304
    const size_t att_elems = (size_t)BB * NHQ * TT * TT;           // 134,217,728
    float* attOut = out + y_elems;
    const int write_att = ((size_t)out_size >= y_elems + att_elems) ? 1 : 0;

    const size_t ATTN_SMEM = (size_t)(16 * 2048 + 128 * 17 * 4 + 16 * 17 * 4 + 16) * sizeof(float);
    cudaFuncSetAttribute(attn_kernel, cudaFuncAttributeMaxDynamicSharedMemorySize,
                         (int)ATTN_SMEM);

    qkv_gemm_kernel<<<dim3(32, 12), 256>>>(x, Wq, bq, Wk, bk, Wv, bv);

    const int qpairs = BB * NHQ * TT * 32;   // 2,097,152
    const int kpairs = BB * NHKV * TT * 32;  //   524,288
    rope_kernel<<<(qpairs + 255) / 256, 256>>>(1, qpairs);
    rope_kernel<<<(kpairs + 255) / 256, 256>>>(0, kpairs);

    attn_kernel<<<dim3(128, 32), 256, ATTN_SMEM>>>(attOut, write_att);

    out_gemm_kernel<<<dim3(32, 8), 256>>>(Wo, bo, out);
}

// round 4
// speedup vs baseline: 1.5951x; 1.5027x over previous
#include <cuda_runtime.h>
#include <math.h>
#include <stdint.h>

#define BB 2
#define TT 2048
#define EE 1024
#define NHQ 16
#define NHKV 4
#define DD 64
#define GG 4

typedef unsigned long long u64;

// ---- packed f32x2 helpers (sm_100+) --------------------------------------
__device__ __forceinline__ u64 pk2(float lo, float hi) {
    u64 r; asm("mov.b64 %0,{%1,%2};" : "=l"(r) : "f"(lo), "f"(hi)); return r;
}
__device__ __forceinline__ float2 upk2(u64 v) {
    float2 f; asm("mov.b64 {%0,%1},%2;" : "=f"(f.x), "=f"(f.y) : "l"(v)); return f;
}
__device__ __forceinline__ void fma2(u64& d, u64 a, u64 b) {
    asm("fma.rn.f32x2 %0,%1,%2,%0;" : "+l"(d) : "l"(a), "l"(b));
}
// ---- cp.async helpers -----------------------------------------------------
__device__ __forceinline__ void cp16(void* s, const void* g) {
    unsigned sa = (unsigned)__cvta_generic_to_shared(s);
    asm volatile("cp.async.ca.shared.global [%0],[%1],16;" :: "r"(sa), "l"(g));
}
__device__ __forceinline__ void cp_commit() {
    asm volatile("cp.async.commit_group;");
}
template<int N> __device__ __forceinline__ void cp_wait() {
    asm volatile("cp.async.wait_group %0;" :: "n"(N));
}

// Scratch (static __device__ per allocation rules)
__device__ float g_q[(size_t)BB*NHQ*TT*DD];   // (b, hq, t, d)
__device__ float g_k[(size_t)BB*NHKV*TT*DD];  // (b, hkv, t, d)
__device__ float g_v[(size_t)BB*NHKV*TT*DD];  // (b, hkv, t, d)
__device__ float g_y[(size_t)BB*TT*EE];       // (b, t, e) attention out pre-Wo
__device__ float g_cs[2][TT][32];             // cos/sin table

// ---------------------------------------------------------------------------
// Fused QKV GEMM: x(4096x1024) @ [Wq|Wk|Wv](1024x1536). FFMA2 + double buffer.
// ---------------------------------------------------------------------------
__global__ void __launch_bounds__(256) qkv_gemm_kernel(
    const float* __restrict__ x,
    const float* __restrict__ Wq, const float* __restrict__ bq,
    const float* __restrict__ Wk, const float* __restrict__ bk,
    const float* __restrict__ Wv, const float* __restrict__ bv)
{
    __shared__ float As[2][8][128];
    __shared__ float Bs[2][8][128];

    const int tid = threadIdx.x;
    const int m0 = blockIdx.x * 128;
    const int n0 = blockIdx.y * 128;   // global col in [0,1536)

    const float* Wmat; const float* bias; int ldw; int ncol0;
    if (n0 < 1024)      { Wmat = Wq; bias = bq; ldw = 1024; ncol0 = n0; }
    else if (n0 < 1280) { Wmat = Wk; bias = bk; ldw = 256;  ncol0 = n0 - 1024; }
    else                { Wmat = Wv; bias = bv; ldw = 256;  ncol0 = n0 - 1280; }

    const int arow = tid >> 1;          // 0..127
    const int acol = (tid & 1) * 4;     // 0 or 4
    const int brow = tid >> 5;          // 0..7
    const int bcol = (tid & 31) * 4;    // 0..124

    const float* Ag = x + (size_t)(m0 + arow) * 1024 + acol;
    const float* Bg = Wmat + (size_t)brow * ldw + ncol0 + bcol;

    const int ty4 = (tid >> 4) * 4;
    const int tx4 = (tid & 15) * 4;

    u64 acc2[8][4];
#pragma unroll
    for (int i = 0; i < 8; i++)
#pragma unroll
        for (int j = 0; j < 4; j++) acc2[i][j] = 0ull;

    // preload tile 0
    float4 av  = *(const float4*)(Ag);
    float4 bv4 = *(const float4*)(Bg);
    As[0][acol + 0][arow] = av.x;
    As[0][acol + 1][arow] = av.y;
    As[0][acol + 2][arow] = av.z;
    As[0][acol + 3][arow] = av.w;
    *(float4*)&Bs[0][brow][bcol] = bv4;
    __syncthreads();

    for (int kt = 0; kt < 128; kt++) {
        const int st = kt & 1;
        if (kt < 127) {
            av  = *(const float4*)(Ag + (kt + 1) * 8);
            bv4 = *(const float4*)(Bg + (size_t)(kt + 1) * 8 * ldw);
        }
#pragma unroll
        for (int kk = 0; kk < 8; kk++) {
            float4 a0 = *(float4*)&As[st][kk][ty4];
            float4 a1 = *(float4*)&As[st][kk][64 + ty4];
            float4 b0 = *(float4*)&Bs[st][kk][tx4];
            float4 b1 = *(float4*)&Bs[st][kk][64 + tx4];
            float ar[8] = {a0.x,a0.y,a0.z,a0.w,a1.x,a1.y,a1.z,a1.w};
            u64 brp[4] = {pk2(b0.x,b0.y), pk2(b0.z,b0.w),
                          pk2(b1.x,b1.y), pk2(b1.z,b1.w)};
#pragma unroll
            for (int i = 0; i < 8; i++) {
                const u64 arp = pk2(ar[i], ar[i]);
#pragma unroll
                for (int j = 0; j < 4; j++)
                    fma2(acc2[i][j], arp, brp[j]);
            }
        }
        if (kt < 127) {
            const int ns = (kt + 1) & 1;
            As[ns][acol + 0][arow] = av.x;
            As[ns][acol + 1][arow] = av.y;
            As[ns][acol + 2][arow] = av.z;
            As[ns][acol + 3][arow] = av.w;
            *(float4*)&Bs[ns][brow][bcol] = bv4;
            __syncthreads();
        }
    }

#pragma unroll
    for (int i = 0; i < 8; i++) {
        const int m = m0 + ((i < 4) ? (ty4 + i) : (64 + ty4 + i - 4));
        const int b = m >> 11;
        const int t = m & 2047;
#pragma unroll
        for (int j4 = 0; j4 < 4; j4++) {
            const float2 v2 = upk2(acc2[i][j4]);
            const int nbase = (j4 < 2) ? (tx4 + 2*j4) : (64 + tx4 + 2*(j4-2));
#pragma unroll
            for (int s = 0; s < 2; s++) {
                const int nloc = nbase + s;
                const int n = n0 + nloc;
                const int ncl = ncol0 + nloc;
                const float val = ((s == 0) ? v2.x : v2.y) + bias[ncl];
                if (n < 1024) {
                    const int head = n >> 6, d = n & 63;
                    g_q[(((size_t)b * NHQ + head) * TT + t) * DD + d] = val;
                } else if (n < 1280) {
                    const int c = n - 1024;
                    g_k[(((size_t)b * NHKV + (c >> 6)) * TT + t) * DD + (c & 63)] = val;
                } else {
                    const int c = n - 1280;
                    g_v[(((size_t)b * NHKV + (c >> 6)) * TT + t) * DD + (c & 63)] = val;
                }
            }
        }
    }
}

// ---------------------------------------------------------------------------
// Out projection: g_y(4096x1024) @ Wo(1024x1024) + bo -> out. Double buffer.
// ---------------------------------------------------------------------------
__global__ void __launch_bounds__(256) out_gemm_kernel(
    const float* __restrict__ Wo, const float* __restrict__ bo,
    float* __restrict__ out)
{
    __shared__ float As[2][8][128];
    __shared__ float Bs[2][8][128];

    const int tid = threadIdx.x;
    const int m0 = blockIdx.x * 128;
    const int n0 = blockIdx.y * 128;

    const int arow = tid >> 1;
    const int acol = (tid & 1) * 4;
    const int brow = tid >> 5;
    const int bcol = (tid & 31) * 4;

    const float* Ag = g_y + (size_t)(m0 + arow) * 1024 + acol;
    const float* Bg = Wo + (size_t)brow * 1024 + n0 + bcol;

    const int ty4 = (tid >> 4) * 4;
    const int tx4 = (tid & 15) * 4;

    u64 acc2[8][4];
#pragma unroll
    for (int i = 0; i < 8; i++)
#pragma unroll
        for (int j = 0; j < 4; j++) acc2[i][j] = 0ull;

    float4 av  = *(const float4*)(Ag);
    float4 bv4 = *(const float4*)(Bg);
    As[0][acol + 0][arow] = av.x;
    As[0][acol + 1][arow] = av.y;
    As[0][acol + 2][arow] = av.z;
    As[0][acol + 3][arow] = av.w;
    *(float4*)&Bs[0][brow][bcol] = bv4;
    __syncthreads();

    for (int kt = 0; kt < 128; kt++) {
        const int st = kt & 1;
        if (kt < 127) {
            av  = *(const float4*)(Ag + (kt + 1) * 8);
            bv4 = *(const float4*)(Bg + (size_t)(kt + 1) * 8 * 1024);
        }
#pragma unroll
        for (int kk = 0; kk < 8; kk++) {
            float4 a0 = *(float4*)&As[st][kk][ty4];
            float4 a1 = *(float4*)&As[st][kk][64 + ty4];
            float4 b0 = *(float4*)&Bs[st][kk][tx4];
            float4 b1 = *(float4*)&Bs[st][kk][64 + tx4];
            float ar[8] = {a0.x,a0.y,a0.z,a0.w,a1.x,a1.y,a1.z,a1.w};
            u64 brp[4] = {pk2(b0.x,b0.y), pk2(b0.z,b0.w),
                          pk2(b1.x,b1.y), pk2(b1.z,b1.w)};
#pragma unroll
            for (int i = 0; i < 8; i++) {
                const u64 arp = pk2(ar[i], ar[i]);
#pragma unroll
                for (int j = 0; j < 4; j++)
                    fma2(acc2[i][j], arp, brp[j]);
            }
        }
        if (kt < 127) {
            const int ns = (kt + 1) & 1;
            As[ns][acol + 0][arow] = av.x;
            As[ns][acol + 1][arow] = av.y;
            As[ns][acol + 2][arow] = av.z;
            As[ns][acol + 3][arow] = av.w;
            *(float4*)&Bs[ns][brow][bcol] = bv4;
            __syncthreads();
        }
    }

#pragma unroll
    for (int i = 0; i < 8; i++) {
        const int m = m0 + ((i < 4) ? (ty4 + i) : (64 + ty4 + i - 4));
#pragma unroll
        for (int j4 = 0; j4 < 4; j4++) {
            const float2 v2 = upk2(acc2[i][j4]);
            const int nbase = (j4 < 2) ? (tx4 + 2*j4) : (64 + tx4 + 2*(j4-2));
            const int n = n0 + nbase;
            out[(size_t)m * 1024 + n]     = v2.x + bo[n];
            out[(size_t)m * 1024 + n + 1] = v2.y + bo[n + 1];
        }
    }
}

// ---------------------------------------------------------------------------
// RoPE: cos/sin table (same math as before), then cheap apply kernels.
// ---------------------------------------------------------------------------
__global__ void rope_table_kernel()
{
    const int idx = blockIdx.x * 256 + threadIdx.x;  // t*32 + p
    if (idx >= TT * 32) return;
    const int p = idx & 31;
    const int t = idx >> 5;
    const double theta_d = pow(10000.0, -(double)p * (1.0 / 32.0));
    const float  theta_f = (float)theta_d;
    const float  ang     = (float)(t + 1) * theta_f;
    const double r       = fmod((double)ang, 6.283185307179586476925287);
    const float  rf      = (float)r;
    g_cs[0][t][p] = cosf(rf);
    g_cs[1][t][p] = sinf(rf);
}

__global__ void rope_apply_kernel(int isq, int total)
{
    const int idx = blockIdx.x * 256 + threadIdx.x;
    if (idx >= total) return;
    float* buf = isq ? g_q : g_k;
    const int p  = idx & 31;
    const int t  = (idx >> 5) & 2047;
    const int bh = idx >> 16;
    float* row = buf + ((size_t)bh * TT + t) * DD;
    const float c = g_cs[0][t][p];
    const float s = g_cs[1][t][p];
    const float x1 = row[p];
    const float x2 = row[p + 32];
    row[p]      = x1 * c - x2 * s;
    row[p + 32] = x2 * c + x1 * s;
}

// ---------------------------------------------------------------------------
// Attention: one CTA per (b, hq, 16-query tile). S (16x2048) in SMEM.
// QK: warp = 4 rows x 64 keys (2/lane), LDS.128 only, cp.async double buffer.
// ---------------------------------------------------------------------------
__device__ __forceinline__ void load_kv_stage(float4* dst, const float* base,
                                              int j0, int tid)
{
#pragma unroll
    for (int i = 0; i < 8; i++) {
        const int idx = tid + i * 256;
        const int row = idx >> 4, col = idx & 15;
        cp16(&dst[row * 17 + col], base + (size_t)(j0 + row) * 64 + col * 4);
    }
    cp_commit();
}

__global__ void __launch_bounds__(256) attn_kernel(float* __restrict__ att_out,
                                                   int write_att)
{
    extern __shared__ float sm[];
    float*  S      = sm;                          // [16][2048]
    float4* kvbuf  = (float4*)(sm + 16 * 2048);   // [2][128][17]
    float4* q4t    = kvbuf + 2 * 128 * 17;        // [16][17]
    float*  rowinv = (float*)(q4t + 16 * 17);     // [16]

    const int qtile = blockIdx.x;                 // 0..127
    const int bh    = blockIdx.y;                 // 0..31
    const int b  = bh >> 4, hq = bh & 15;
    const int h  = hq >> 2, g  = hq & 3;
    const int tid  = threadIdx.x;
    const int warp = tid >> 5, lane = tid & 31;

    const float* qbase = g_q + (((size_t)(b * NHQ + hq)) * TT + qtile * 16) * DD;
    const float* kbase = g_k + ((size_t)(b * NHKV + h)) * TT * DD;
    const float* vbase = g_v + ((size_t)(b * NHKV + h)) * TT * DD;

    const int tq_hi  = qtile * 16 + 15;
    const int ntiles = tq_hi / 128 + 1;           // 128-wide tiles
    const int Jlim   = ntiles * 128;

    // kick off K tile 0 while we stage q
    load_kv_stage(kvbuf, kbase, 0, tid);

    // load q tile (scaled by 1/sqrt(D))
    {
        const int r = tid >> 4, c = tid & 15;
        float4 qv = *(const float4*)(qbase + r * 64 + c * 4);
        qv.x *= 0.125f; qv.y *= 0.125f; qv.z *= 0.125f; qv.w *= 0.125f;
        q4t[r * 17 + c] = qv;
    }

    // ---- QK^T: warp = 4 rows (rg) x 64 keys (kg half), 2 keys/lane
    const int rg = warp & 3;            // row group: rows rg*4 .. rg*4+3
    const int kg = warp >> 2;           // key group: keys kg*64 .. kg*64+63
    const int r0 = rg * 4;

    for (int kt = 0; kt < ntiles; kt++) {
        const int j0 = kt * 128;
        if (kt + 1 < ntiles) {
            load_kv_stage(kvbuf + ((kt + 1) & 1) * 128 * 17, kbase,
                          (kt + 1) * 128, tid);
            cp_wait<1>();
        } else {
            cp_wait<0>();
        }
        __syncthreads();

        const float4* kvst = kvbuf + (kt & 1) * 128 * 17;
        const float4* kAp = kvst + (kg * 64 + lane) * 17;
        const float4* kBp = kAp + 32 * 17;

        u64 acc[4][2];
#pragma unroll
        for (int r = 0; r < 4; r++) { acc[r][0] = 0ull; acc[r][1] = 0ull; }

#pragma unroll
        for (int cc = 0; cc < 16; cc++) {
            const float4 ka = kAp[cc];
            const float4 kb = kBp[cc];
            const u64 ka0 = pk2(ka.x, ka.y), ka1 = pk2(ka.z, ka.w);
            const u64 kb0 = pk2(kb.x, kb.y), kb1 = pk2(kb.z, kb.w);
#pragma unroll
            for (int r = 0; r < 4; r++) {
                const float4 qv = q4t[(r0 + r) * 17 + cc];
                const u64 qa0 = pk2(qv.x, qv.y), qa1 = pk2(qv.z, qv.w);
                fma2(acc[r][0], qa0, ka0); fma2(acc[r][0], qa1, ka1);
                fma2(acc[r][1], qa0, kb0); fma2(acc[r][1], qa1, kb1);
            }
        }
#pragma unroll
        for (int r = 0; r < 4; r++) {
            const float2 a = upk2(acc[r][0]);
            const float2 c2 = upk2(acc[r][1]);
            S[(r0 + r) * 2048 + j0 + kg * 64 + lane]      = a.x + a.y;
            S[(r0 + r) * 2048 + j0 + kg * 64 + 32 + lane] = c2.x + c2.y;
        }
        __syncthreads();
    }

    // prefetch V tile 0, overlapping with softmax
    load_kv_stage(kvbuf, vbase, 0, tid);

    // ---- softmax per row (causal): warp handles rows 2w, 2w+1
#pragma unroll
    for (int rr = 0; rr < 2; rr++) {
        const int r  = warp * 2 + rr;
        const int tq = qtile * 16 + r;
        const int L  = tq + 1;
        float m = -3.4e38f;
        for (int j = lane; j < L; j += 32) m = fmaxf(m, S[r * 2048 + j]);
#pragma unroll
        for (int o = 16; o; o >>= 1) m = fmaxf(m, __shfl_xor_sync(0xffffffffu, m, o));
        float sum = 0.f;
        for (int j = lane; j < Jlim; j += 32) {
            const float sv = S[r * 2048 + j];
            const float e  = (j < L) ? __expf(sv - m) : 0.f;
            S[r * 2048 + j] = e;
            sum += e;
        }
#pragma unroll
        for (int o = 16; o; o >>= 1) sum += __shfl_xor_sync(0xffffffffu, sum, o);
        const float inv = 1.f / sum;
        if (lane == 0) rowinv[r] = inv;
        if (write_att) {
            float* orow = att_out + ((((size_t)b * GG + g) * NHKV + h) * TT + tq) * TT;
            for (int j4 = lane * 4; j4 < Jlim; j4 += 128) {
                float4 e4 = *(float4*)&S[r * 2048 + j4];
                e4.x *= inv; e4.y *= inv; e4.z *= inv; e4.w *= inv;
                *(float4*)&orow[j4] = e4;
            }
            const float4 z4 = make_float4(0.f, 0.f, 0.f, 0.f);
            for (int j4 = Jlim + lane * 4; j4 < TT; j4 += 128)
                *(float4*)&orow[j4] = z4;
        }
    }

    // ---- PV: thread = (dim chunk dc, j segment js); 16 query accumulators
    const int dc = tid & 15;
    const int js = tid >> 4;
    u64 accP[16][2];
#pragma unroll
    for (int q = 0; q < 16; q++) { accP[q][0] = 0ull; accP[q][1] = 0ull; }

    for (int kt = 0; kt < ntiles; kt++) {
        const int j0 = kt * 128;
        if (kt + 1 < ntiles) {
            load_kv_stage(kvbuf + ((kt + 1) & 1) * 128 * 17, vbase,
                          (kt + 1) * 128, tid);
            cp_wait<1>();
        } else {
            cp_wait<0>();
        }
        __syncthreads();

        const float4* kvst = kvbuf + (kt & 1) * 128 * 17;
#pragma unroll
        for (int u = 0; u < 8; u++) {
            const int jj = js + u * 16;
            const float4 vv = kvst[jj * 17 + dc];
            const u64 v0 = pk2(vv.x, vv.y);
            const u64 v1 = pk2(vv.z, vv.w);
#pragma unroll
            for (int q = 0; q < 16; q++) {
                const float e = S[q * 2048 + j0 + jj];
                const u64 ep = pk2(e, e);
                fma2(accP[q][0], ep, v0);
                fma2(accP[q][1], ep, v1);
            }
        }
        __syncthreads();
    }

    // reduce over js (16 partials per (q,dc)); reuse S as scratch
    float4* P = (float4*)S;   // [js][q*16+dc] : 16*256 float4 = 64KB
#pragma unroll
    for (int q = 0; q < 16; q++) {
        const float2 xy = upk2(accP[q][0]);
        const float2 zw = upk2(accP[q][1]);
        P[js * 256 + q * 16 + dc] = make_float4(xy.x, xy.y, zw.x, zw.y);
    }
    __syncthreads();
    {
        const int q2 = tid >> 4, dc2 = tid & 15;
        float4 r4 = make_float4(0.f, 0.f, 0.f, 0.f);
#pragma unroll
        for (int js2 = 0; js2 < 16; js2++) {
            const float4 pv = P[js2 * 256 + q2 * 16 + dc2];
            r4.x += pv.x; r4.y += pv.y; r4.z += pv.z; r4.w += pv.w;
        }
        const float inv = rowinv[q2];
        r4.x *= inv; r4.y *= inv; r4.z *= inv; r4.w *= inv;
        const int tq = qtile * 16 + q2;
        float* ydst = g_y + ((size_t)b * TT + tq) * EE + hq * 64 + dc2 * 4;
        *(float4*)ydst = r4;
    }
}

// ---------------------------------------------------------------------------
extern "C" void kernel_launch(void* const* d_in, const int* in_sizes, int n_in,
                              void* d_out, int out_size)
{
    const float* x  = (const float*)d_in[0];
    // d_in[1] = mask (int32, triu(...,1)) -> causal, handled analytically
    const float* Wq = (const float*)d_in[2];
    const float* bq = (const float*)d_in[3];
    const float* Wk = (const float*)d_in[4];
    const float* bk = (const float*)d_in[5];
    const float* Wv = (const float*)d_in[6];
    const float* bv = (const float*)d_in[7];
    const float* Wo = (const float*)d_in[8];
    const float* bo = (const float*)d_in[9];

    float* out = (float*)d_out;
    const size_t y_elems   = (size_t)BB * TT * EE;
    const size_t att_elems = (size_t)BB * NHQ * TT * TT;
    float* attOut = out + y_elems;
    const int write_att = ((size_t)out_size >= y_elems + att_elems) ? 1 : 0;

    const size_t ATTN_SMEM = (size_t)(16 * 2048 + 2 * 128 * 17 * 4 + 16 * 17 * 4 + 16) * sizeof(float);
    cudaFuncSetAttribute(attn_kernel, cudaFuncAttributeMaxDynamicSharedMemorySize,
                         (int)ATTN_SMEM);

    rope_table_kernel<<<(TT * 32 + 255) / 256, 256>>>();

    qkv_gemm_kernel<<<dim3(32, 12), 256>>>(x, Wq, bq, Wk, bk, Wv, bv);

    const int qpairs = BB * NHQ * TT * 32;   // 2,097,152
    const int kpairs = BB * NHKV * TT * 32;  //   524,288
    rope_apply_kernel<<<(qpairs + 255) / 256, 256>>>(1, qpairs);
    rope_apply_kernel<<<(kpairs + 255) / 256, 256>>>(0, kpairs);

    attn_kernel<<<dim3(128, 32), 256, ATTN_SMEM>>>(attOut, write_att);

    out_gemm_kernel<<<dim3(32, 8), 256>>>(Wo, bo, out);
}

// round 7
// speedup vs baseline: 1.9002x; 1.1913x over previous
#include <cuda_runtime.h>
#include <math.h>
#include <stdint.h>

#define BB 2
#define TT 2048
#define EE 1024
#define NHQ 16
#define NHKV 4
#define DD 64
#define GG 4

typedef unsigned long long u64;

// ---- packed f32x2 helpers (sm_100+) --------------------------------------
__device__ __forceinline__ u64 pk2(float lo, float hi) {
    u64 r; asm("mov.b64 %0,{%1,%2};" : "=l"(r) : "f"(lo), "f"(hi)); return r;
}
__device__ __forceinline__ float2 upk2(u64 v) {
    float2 f; asm("mov.b64 {%0,%1},%2;" : "=f"(f.x), "=f"(f.y) : "l"(v)); return f;
}
__device__ __forceinline__ void fma2(u64& d, u64 a, u64 b) {
    asm("fma.rn.f32x2 %0,%1,%2,%0;" : "+l"(d) : "l"(a), "l"(b));
}
// ---- cp.async helpers -----------------------------------------------------
__device__ __forceinline__ void cp16(void* s, const void* g) {
    unsigned sa = (unsigned)__cvta_generic_to_shared(s);
    asm volatile("cp.async.ca.shared.global [%0],[%1],16;" :: "r"(sa), "l"(g));
}
__device__ __forceinline__ void cp_commit() {
    asm volatile("cp.async.commit_group;");
}
template<int N> __device__ __forceinline__ void cp_wait() {
    asm volatile("cp.async.wait_group %0;" :: "n"(N));
}
// ---- tf32 mma helpers ------------------------------------------------------
__device__ __forceinline__ unsigned to_tf32(float f) {
    unsigned r; asm("cvt.rna.tf32.f32 %0,%1;" : "=r"(r) : "f"(f)); return r;
}
__device__ __forceinline__ void mma_tf32(float* c, const unsigned* a, const unsigned* b) {
    asm volatile(
        "mma.sync.aligned.m16n8k8.row.col.f32.tf32.tf32.f32 "
        "{%0,%1,%2,%3},{%4,%5,%6,%7},{%8,%9},{%0,%1,%2,%3};"
        : "+f"(c[0]), "+f"(c[1]), "+f"(c[2]), "+f"(c[3])
        : "r"(a[0]), "r"(a[1]), "r"(a[2]), "r"(a[3]), "r"(b[0]), "r"(b[1]));
}

// Scratch (static __device__ per allocation rules)
__device__ float g_q[(size_t)BB*NHQ*TT*DD];   // (b, hq, t, d)
__device__ float g_k[(size_t)BB*NHKV*TT*DD];  // (b, hkv, t, d)
__device__ float g_v[(size_t)BB*NHKV*TT*DD];  // (b, hkv, t, d)
__device__ float g_y[(size_t)BB*TT*EE];       // (b, t, e) attention out pre-Wo
__device__ float g_cs[2][TT][32];             // cos/sin table

// GEMM tiling
#define BM 128
#define BN 128
#define BK 32
#define A_STRIDE 36
#define B_STRIDE 132
#define GEMM_SMEM ((2*BM*A_STRIDE + 2*BK*B_STRIDE) * 4)

// ---------------------------------------------------------------------------
// tf32 tensor-core GEMM core. Computes C(128x128) = A(128xK) @ W(KxN tile).
// 256 threads = 8 warps (2x4); warp tile 64x32 = 4 m16 x 4 n8.
// ---------------------------------------------------------------------------
struct GemmFrag { float c[4][4][4]; };   // [mt][nt][reg]

__device__ __forceinline__ void gemm_tile_tf32(
    float* sm, const float* __restrict__ Aglob, int lda,
    const float* __restrict__ Wglob, int ldw, int ncol0,
    int m0, int nK, GemmFrag& F)
{
    float* As = sm;                       // [2][BM][A_STRIDE]
    float* Bs = sm + 2 * BM * A_STRIDE;   // [2][BK][B_STRIDE]

    const int tid = threadIdx.x;
    const int warp = tid >> 5, lane = tid & 31;
    const int warpM = warp >> 2, warpN = warp & 3;
    const int lr = lane >> 2, lc = lane & 3;

#pragma unroll
    for (int mt = 0; mt < 4; mt++)
#pragma unroll
        for (int nt = 0; nt < 4; nt++)
#pragma unroll
            for (int r = 0; r < 4; r++) F.c[mt][nt][r] = 0.f;

    const int ntiles = nK / BK;

    // load tile 0
    {
        const int m = tid >> 3, kq = (tid & 7) * 4;
#pragma unroll
        for (int i = 0; i < 4; i++)
            cp16(&As[(i*32 + m) * A_STRIDE + kq],
                 Aglob + (size_t)(m0 + i*32 + m) * lda + kq);
        const int kr = tid >> 5, c4 = (tid & 31) * 4;
#pragma unroll
        for (int i = 0; i < 4; i++)
            cp16(&Bs[(i*8 + kr) * B_STRIDE + c4],
                 Wglob + (size_t)(i*8 + kr) * ldw + ncol0 + c4);
        cp_commit();
    }

    for (int kt = 0; kt < ntiles; kt++) {
        if (kt + 1 < ntiles) {
            const int st = ((kt + 1) & 1);
            const int m = tid >> 3, kq = (tid & 7) * 4;
#pragma unroll
            for (int i = 0; i < 4; i++)
                cp16(&As[st*BM*A_STRIDE + (i*32 + m) * A_STRIDE + kq],
                     Aglob + (size_t)(m0 + i*32 + m) * lda + (kt+1)*BK + kq);
            const int kr = tid >> 5, c4 = (tid & 31) * 4;
#pragma unroll
            for (int i = 0; i < 4; i++)
                cp16(&Bs[st*BK*B_STRIDE + (i*8 + kr) * B_STRIDE + c4],
                     Wglob + (size_t)((kt+1)*BK + i*8 + kr) * ldw + ncol0 + c4);
            cp_commit();
            cp_wait<1>();
        } else {
            cp_wait<0>();
        }
        __syncthreads();

        const float* Ast = As + (kt & 1) * BM * A_STRIDE;
        const float* Bst = Bs + (kt & 1) * BK * B_STRIDE;

#pragma unroll
        for (int ks = 0; ks < 4; ks++) {
            const int k0 = ks * 8;
            unsigned afr[4][4];
#pragma unroll
            for (int mt = 0; mt < 4; mt++) {
                const int r0 = warpM * 64 + mt * 16 + lr;
                afr[mt][0] = to_tf32(Ast[(r0    ) * A_STRIDE + k0 + lc]);
                afr[mt][1] = to_tf32(Ast[(r0 + 8) * A_STRIDE + k0 + lc]);
                afr[mt][2] = to_tf32(Ast[(r0    ) * A_STRIDE + k0 + lc + 4]);
                afr[mt][3] = to_tf32(Ast[(r0 + 8) * A_STRIDE + k0 + lc + 4]);
            }
            unsigned bfr[4][2];
#pragma unroll
            for (int nt = 0; nt < 4; nt++) {
                const int c0 = warpN * 32 + nt * 8 + lr;
                bfr[nt][0] = to_tf32(Bst[(k0 + lc    ) * B_STRIDE + c0]);
                bfr[nt][1] = to_tf32(Bst[(k0 + lc + 4) * B_STRIDE + c0]);
            }
#pragma unroll
            for (int mt = 0; mt < 4; mt++)
#pragma unroll
                for (int nt = 0; nt < 4; nt++)
                    mma_tf32(F.c[mt][nt], afr[mt], bfr[nt]);
        }
        __syncthreads();
    }
}

// ---------------------------------------------------------------------------
// Fused QKV GEMM (tf32 tensor cores) with head-scatter epilogue.
// ---------------------------------------------------------------------------
__global__ void __launch_bounds__(256) qkv_gemm_kernel(
    const float* __restrict__ x,
    const float* __restrict__ Wq, const float* __restrict__ bq,
    const float* __restrict__ Wk, const float* __restrict__ bk,
    const float* __restrict__ Wv, const float* __restrict__ bv)
{
    extern __shared__ float sm[];
    const int m0 = blockIdx.x * BM;
    const int n0 = blockIdx.y * BN;

    const float* Wmat; const float* bias; int ldw; int ncol0;
    if (n0 < 1024)      { Wmat = Wq; bias = bq; ldw = 1024; ncol0 = n0; }
    else if (n0 < 1280) { Wmat = Wk; bias = bk; ldw = 256;  ncol0 = n0 - 1024; }
    else                { Wmat = Wv; bias = bv; ldw = 256;  ncol0 = n0 - 1280; }

    GemmFrag F;
    gemm_tile_tf32(sm, x, 1024, Wmat, ldw, ncol0, m0, 1024, F);

    const int tid = threadIdx.x;
    const int warp = tid >> 5, lane = tid & 31;
    const int warpM = warp >> 2, warpN = warp & 3;
    const int lr = lane >> 2, lc = lane & 3;

#pragma unroll
    for (int mt = 0; mt < 4; mt++) {
        const int rbase = m0 + warpM * 64 + mt * 16 + lr;
#pragma unroll
        for (int nt = 0; nt < 4; nt++) {
            const int nl0 = warpN * 32 + nt * 8 + 2 * lc;
#pragma unroll
            for (int r = 0; r < 4; r++) {
                const int m = rbase + ((r >= 2) ? 8 : 0);
                const int nl = nl0 + (r & 1);
                const int n = n0 + nl;
                const int ncl = ncol0 + nl;
                const float val = F.c[mt][nt][r] + bias[ncl];
                const int b = m >> 11, t = m & 2047;
                if (n < 1024) {
                    const int head = n >> 6, d = n & 63;
                    g_q[(((size_t)b * NHQ + head) * TT + t) * DD + d] = val;
                } else if (n < 1280) {
                    const int c = n - 1024;
                    g_k[(((size_t)b * NHKV + (c >> 6)) * TT + t) * DD + (c & 63)] = val;
                } else {
                    const int c = n - 1280;
                    g_v[(((size_t)b * NHKV + (c >> 6)) * TT + t) * DD + (c & 63)] = val;
                }
            }
        }
    }
}

// ---------------------------------------------------------------------------
// Out projection (tf32 tensor cores): g_y @ Wo + bo -> out.
// ---------------------------------------------------------------------------
__global__ void __launch_bounds__(256) out_gemm_kernel(
    const float* __restrict__ Wo, const float* __restrict__ bo,
    float* __restrict__ out)
{
    extern __shared__ float sm[];
    const int m0 = blockIdx.x * BM;
    const int n0 = blockIdx.y * BN;

    GemmFrag F;
    gemm_tile_tf32(sm, g_y, 1024, Wo, 1024, n0, m0, 1024, F);

    const int tid = threadIdx.x;
    const int warp = tid >> 5, lane = tid & 31;
    const int warpM = warp >> 2, warpN = warp & 3;
    const int lr = lane >> 2, lc = lane & 3;

#pragma unroll
    for (int mt = 0; mt < 4; mt++) {
        const int rbase = m0 + warpM * 64 + mt * 16 + lr;
#pragma unroll
        for (int nt = 0; nt < 4; nt++) {
            const int n = n0 + warpN * 32 + nt * 8 + 2 * lc;
            out[(size_t)rbase * 1024 + n]            = F.c[mt][nt][0] + bo[n];
            out[(size_t)rbase * 1024 + n + 1]        = F.c[mt][nt][1] + bo[n + 1];
            out[(size_t)(rbase + 8) * 1024 + n]      = F.c[mt][nt][2] + bo[n];
            out[(size_t)(rbase + 8) * 1024 + n + 1]  = F.c[mt][nt][3] + bo[n + 1];
        }
    }
}

// ---------------------------------------------------------------------------
// RoPE: cos/sin table, then cheap apply kernels.
// ---------------------------------------------------------------------------
__global__ void rope_table_kernel()
{
    const int idx = blockIdx.x * 256 + threadIdx.x;  // t*32 + p
    if (idx >= TT * 32) return;
    const int p = idx & 31;
    const int t = idx >> 5;
    const double theta_d = pow(10000.0, -(double)p * (1.0 / 32.0));
    const float  theta_f = (float)theta_d;
    const float  ang     = (float)(t + 1) * theta_f;
    const double r       = fmod((double)ang, 6.283185307179586476925287);
    const float  rf      = (float)r;
    g_cs[0][t][p] = cosf(rf);
    g_cs[1][t][p] = sinf(rf);
}

__global__ void rope_apply_kernel(int isq, int total)
{
    const int idx = blockIdx.x * 256 + threadIdx.x;
    if (idx >= total) return;
    float* buf = isq ? g_q : g_k;
    const int p  = idx & 31;
    const int t  = (idx >> 5) & 2047;
    const int bh = idx >> 16;
    float* row = buf + ((size_t)bh * TT + t) * DD;
    const float c = g_cs[0][t][p];
    const float s = g_cs[1][t][p];
    const float x1 = row[p];
    const float x2 = row[p + 32];
    row[p]      = x1 * c - x2 * s;
    row[p + 32] = x2 * c + x1 * s;
}

// ---------------------------------------------------------------------------
// Attention (unchanged from R4): one CTA per (b, hq, 16-query tile).
// ---------------------------------------------------------------------------
__device__ __forceinline__ void load_kv_stage(float4* dst, const float* base,
                                              int j0, int tid)
{
#pragma unroll
    for (int i = 0; i < 8; i++) {
        const int idx = tid + i * 256;
        const int row = idx >> 4, col = idx & 15;
        cp16(&dst[row * 17 + col], base + (size_t)(j0 + row) * 64 + col * 4);
    }
    cp_commit();
}

__global__ void __launch_bounds__(256) attn_kernel(float* __restrict__ att_out,
                                                   int write_att)
{
    extern __shared__ float sma[];
    float*  S      = sma;                          // [16][2048]
    float4* kvbuf  = (float4*)(sma + 16 * 2048);   // [2][128][17]
    float4* q4t    = kvbuf + 2 * 128 * 17;         // [16][17]
    float*  rowinv = (float*)(q4t + 16 * 17);      // [16]

    const int qtile = blockIdx.x;                  // 0..127
    const int bh    = blockIdx.y;                  // 0..31
    const int b  = bh >> 4, hq = bh & 15;
    const int h  = hq >> 2, g  = hq & 3;
    const int tid  = threadIdx.x;
    const int warp = tid >> 5, lane = tid & 31;

    const float* qbase = g_q + (((size_t)(b * NHQ + hq)) * TT + qtile * 16) * DD;
    const float* kbase = g_k + ((size_t)(b * NHKV + h)) * TT * DD;
    const float* vbase = g_v + ((size_t)(b * NHKV + h)) * TT * DD;

    const int tq_hi  = qtile * 16 + 15;
    const int ntiles = tq_hi / 128 + 1;
    const int Jlim   = ntiles * 128;

    load_kv_stage(kvbuf, kbase, 0, tid);

    {
        const int r = tid >> 4, c = tid & 15;
        float4 qv = *(const float4*)(qbase + r * 64 + c * 4);
        qv.x *= 0.125f; qv.y *= 0.125f; qv.z *= 0.125f; qv.w *= 0.125f;
        q4t[r * 17 + c] = qv;
    }

    const int rg = warp & 3;
    const int kg = warp >> 2;
    const int r0 = rg * 4;

    for (int kt = 0; kt < ntiles; kt++) {
        const int j0 = kt * 128;
        if (kt + 1 < ntiles) {
            load_kv_stage(kvbuf + ((kt + 1) & 1) * 128 * 17, kbase,
                          (kt + 1) * 128, tid);
            cp_wait<1>();
        } else {
            cp_wait<0>();
        }
        __syncthreads();

        const float4* kvst = kvbuf + (kt & 1) * 128 * 17;
        const float4* kAp = kvst + (kg * 64 + lane) * 17;
        const float4* kBp = kAp + 32 * 17;

        u64 acc[4][2];
#pragma unroll
        for (int r = 0; r < 4; r++) { acc[r][0] = 0ull; acc[r][1] = 0ull; }

#pragma unroll
        for (int cc = 0; cc < 16; cc++) {
            const float4 ka = kAp[cc];
            const float4 kb = kBp[cc];
            const u64 ka0 = pk2(ka.x, ka.y), ka1 = pk2(ka.z, ka.w);
            const u64 kb0 = pk2(kb.x, kb.y), kb1 = pk2(kb.z, kb.w);
#pragma unroll
            for (int r = 0; r < 4; r++) {
                const float4 qv = q4t[(r0 + r) * 17 + cc];
                const u64 qa0 = pk2(qv.x, qv.y), qa1 = pk2(qv.z, qv.w);
                fma2(acc[r][0], qa0, ka0); fma2(acc[r][0], qa1, ka1);
                fma2(acc[r][1], qa0, kb0); fma2(acc[r][1], qa1, kb1);
            }
        }
#pragma unroll
        for (int r = 0; r < 4; r++) {
            const float2 a = upk2(acc[r][0]);
            const float2 c2 = upk2(acc[r][1]);
            S[(r0 + r) * 2048 + j0 + kg * 64 + lane]      = a.x + a.y;
            S[(r0 + r) * 2048 + j0 + kg * 64 + 32 + lane] = c2.x + c2.y;
        }
        __syncthreads();
    }

    load_kv_stage(kvbuf, vbase, 0, tid);

#pragma unroll
    for (int rr = 0; rr < 2; rr++) {
        const int r  = warp * 2 + rr;
        const int tq = qtile * 16 + r;
        const int L  = tq + 1;
        float m = -3.4e38f;
        for (int j = lane; j < L; j += 32) m = fmaxf(m, S[r * 2048 + j]);
#pragma unroll
        for (int o = 16; o; o >>= 1) m = fmaxf(m, __shfl_xor_sync(0xffffffffu, m, o));
        float sum = 0.f;
        for (int j = lane; j < Jlim; j += 32) {
            const float sv = S[r * 2048 + j];
            const float e  = (j < L) ? __expf(sv - m) : 0.f;
            S[r * 2048 + j] = e;
            sum += e;
        }
#pragma unroll
        for (int o = 16; o; o >>= 1) sum += __shfl_xor_sync(0xffffffffu, sum, o);
        const float inv = 1.f / sum;
        if (lane == 0) rowinv[r] = inv;
        if (write_att) {
            float* orow = att_out + ((((size_t)b * GG + g) * NHKV + h) * TT + tq) * TT;
            for (int j4 = lane * 4; j4 < Jlim; j4 += 128) {
                float4 e4 = *(float4*)&S[r * 2048 + j4];
                e4.x *= inv; e4.y *= inv; e4.z *= inv; e4.w *= inv;
                *(float4*)&orow[j4] = e4;
            }
            const float4 z4 = make_float4(0.f, 0.f, 0.f, 0.f);
            for (int j4 = Jlim + lane * 4; j4 < TT; j4 += 128)
                *(float4*)&orow[j4] = z4;
        }
    }

    const int dc = tid & 15;
    const int js = tid >> 4;
    u64 accP[16][2];
#pragma unroll
    for (int q = 0; q < 16; q++) { accP[q][0] = 0ull; accP[q][1] = 0ull; }

    for (int kt = 0; kt < ntiles; kt++) {
        const int j0 = kt * 128;
        if (kt + 1 < ntiles) {
            load_kv_stage(kvbuf + ((kt + 1) & 1) * 128 * 17, vbase,
                          (kt + 1) * 128, tid);
            cp_wait<1>();
        } else {
            cp_wait<0>();
        }
        __syncthreads();

        const float4* kvst = kvbuf + (kt & 1) * 128 * 17;
#pragma unroll
        for (int u = 0; u < 8; u++) {
            const int jj = js + u * 16;
            const float4 vv = kvst[jj * 17 + dc];
            const u64 v0 = pk2(vv.x, vv.y);
            const u64 v1 = pk2(vv.z, vv.w);
#pragma unroll
            for (int q = 0; q < 16; q++) {
                const float e = S[q * 2048 + j0 + jj];
                const u64 ep = pk2(e, e);
                fma2(accP[q][0], ep, v0);
                fma2(accP[q][1], ep, v1);
            }
        }
        __syncthreads();
    }

    float4* P = (float4*)S;
#pragma unroll
    for (int q = 0; q < 16; q++) {
        const float2 xy = upk2(accP[q][0]);
        const float2 zw = upk2(accP[q][1]);
        P[js * 256 + q * 16 + dc] = make_float4(xy.x, xy.y, zw.x, zw.y);
    }
    __syncthreads();
    {
        const int q2 = tid >> 4, dc2 = tid & 15;
        float4 r4 = make_float4(0.f, 0.f, 0.f, 0.f);
#pragma unroll
        for (int js2 = 0; js2 < 16; js2++) {
            const float4 pv = P[js2 * 256 + q2 * 16 + dc2];
            r4.x += pv.x; r4.y += pv.y; r4.z += pv.z; r4.w += pv.w;
        }
        const float inv = rowinv[q2];
        r4.x *= inv; r4.y *= inv; r4.z *= inv; r4.w *= inv;
        const int tq = qtile * 16 + q2;
        float* ydst = g_y + ((size_t)b * TT + tq) * EE + hq * 64 + dc2 * 4;
        *(float4*)ydst = r4;
    }
}

// ---------------------------------------------------------------------------
extern "C" void kernel_launch(void* const* d_in, const int* in_sizes, int n_in,
                              void* d_out, int out_size)
{
    const float* x  = (const float*)d_in[0];
    // d_in[1] = mask (int32, triu(...,1)) -> causal, handled analytically
    const float* Wq = (const float*)d_in[2];
    const float* bq = (const float*)d_in[3];
    const float* Wk = (const float*)d_in[4];
    const float* bk = (const float*)d_in[5];
    const float* Wv = (const float*)d_in[6];
    const float* bv = (const float*)d_in[7];
    const float* Wo = (const float*)d_in[8];
    const float* bo = (const float*)d_in[9];

    float* out = (float*)d_out;
    const size_t y_elems   = (size_t)BB * TT * EE;
    const size_t att_elems = (size_t)BB * NHQ * TT * TT;
    float* attOut = out + y_elems;
    const int write_att = ((size_t)out_size >= y_elems + att_elems) ? 1 : 0;

    const size_t ATTN_SMEM = (size_t)(16 * 2048 + 2 * 128 * 17 * 4 + 16 * 17 * 4 + 16) * sizeof(float);
    cudaFuncSetAttribute(attn_kernel, cudaFuncAttributeMaxDynamicSharedMemorySize,
                         (int)ATTN_SMEM);
    cudaFuncSetAttribute(qkv_gemm_kernel, cudaFuncAttributeMaxDynamicSharedMemorySize,
                         GEMM_SMEM);
    cudaFuncSetAttribute(out_gemm_kernel, cudaFuncAttributeMaxDynamicSharedMemorySize,
                         GEMM_SMEM);

    rope_table_kernel<<<(TT * 32 + 255) / 256, 256>>>();

    qkv_gemm_kernel<<<dim3(32, 12), 256, GEMM_SMEM>>>(x, Wq, bq, Wk, bk, Wv, bv);

    const int qpairs = BB * NHQ * TT * 32;
    const int kpairs = BB * NHKV * TT * 32;
    rope_apply_kernel<<<(qpairs + 255) / 256, 256>>>(1, qpairs);
    rope_apply_kernel<<<(kpairs + 255) / 256, 256>>>(0, kpairs);

    attn_kernel<<<dim3(128, 32), 256, ATTN_SMEM>>>(attOut, write_att);

    out_gemm_kernel<<<dim3(32, 8), 256, GEMM_SMEM>>>(Wo, bo, out);
}